// round 14
// baseline (speedup 1.0000x reference)
#include <cuda_runtime.h>

// PatchesCreate: [64, 384, 384, 3] f32 -> [64, 576, 768] f32
// Mirror variant of the converged float8/U=4 kernel: threads enumerate the
// INPUT linearly (perfectly sequential LDG.E.256 stream) and scatter the
// stores in 192B runs (6 full sectors each, fire-and-forget). Rationale:
// loads are latency/prefetch sensitive, stores are not — put the scatter
// on the write side.

static constexpr int TOTAL8 = 64 * 384 * 144;  // 3,538,944 x 32B (input units)
static constexpr int TPB    = 256;
static constexpr int UNROLL = 4;
static constexpr int TILE   = TPB * UNROLL;    // 1024
static constexpr int BLOCKS = TOTAL8 / TILE;   // 3456 exactly, no tail

// i in float8 (32B) units over the INPUT [b][y=384][144]; returns the
// corresponding float8 offset in the output [b][patch=576][96].
__device__ __forceinline__ long long out_off8(int i)
{
    int row = i % 144;            // float8 within image row
    int t   = i / 144;
    int y   = t % 384;
    int b   = t / 384;

    int gx   = row / 6;
    int lane = row - gx * 6;
    int gy   = y >> 4;            // y / 16
    int py   = y & 15;            // y % 16

    int patch = gy * 24 + gx;
    return (long long)(b * 576 + patch) * 96 + py * 6 + lane;
}

__device__ __forceinline__ void ldg256(const float* p, float4& a, float4& b)
{
    asm volatile("ld.global.nc.v8.f32 {%0,%1,%2,%3,%4,%5,%6,%7}, [%8];"
                 : "=f"(a.x), "=f"(a.y), "=f"(a.z), "=f"(a.w),
                   "=f"(b.x), "=f"(b.y), "=f"(b.z), "=f"(b.w)
                 : "l"(p));
}

__device__ __forceinline__ void stg256(float* p, const float4& a, const float4& b)
{
    asm volatile("st.global.v8.f32 [%0], {%1,%2,%3,%4,%5,%6,%7,%8};"
                 :: "l"(p),
                    "f"(a.x), "f"(a.y), "f"(a.z), "f"(a.w),
                    "f"(b.x), "f"(b.y), "f"(b.z), "f"(b.w)
                 : "memory");
}

__global__ void __launch_bounds__(TPB)
patches_kernel(const float* __restrict__ in, float* __restrict__ out)
{
    int base = blockIdx.x * TILE + threadIdx.x;

    // Sequential read stream, front-batched for MLP.
    float4 a[UNROLL], b[UNROLL];
#pragma unroll
    for (int u = 0; u < UNROLL; ++u)
        ldg256(in + (long long)(base + u * TPB) * 8, a[u], b[u]);

    // Scattered (192B-run) writes.
#pragma unroll
    for (int u = 0; u < UNROLL; ++u)
        stg256(out + out_off8(base + u * TPB) * 8, a[u], b[u]);
}

extern "C" void kernel_launch(void* const* d_in, const int* in_sizes, int n_in,
                              void* d_out, int out_size)
{
    (void)in_sizes; (void)n_in; (void)out_size;
    const float* in  = (const float*)d_in[0];
    float*       out = (float*)d_out;

    patches_kernel<<<BLOCKS, TPB>>>(in, out);
}

// round 15
// speedup vs baseline: 1.0164x; 1.0164x over previous
#include <cuda_runtime.h>

// PatchesCreate: [64, 384, 384, 3] f32 -> [64, 576, 768] f32
// FINAL converged kernel (13 experiments; see journal). Direct permutation
// copy in 256-bit (float8 = 32B) units: patch row = 192B = 6 x 32B chunks,
// 32B-aligned in both tensors, so the op is a pure float8 permutation.
// Per-thread: 4 independent front-batched LDG.E.256 (measured-optimal MLP:
// U=2 32.9us / U=4 29.5us / U=8 30.3us), then 4 plain STG.E.256.
// Flat grid 3456 CTAs, no tail, 32 regs, occ ~82%.
// Measured equivalent/worse: SMEM staging, cp.async, persistent+pipelined,
// .cs hints, input-sequential mirror, finer/coarser grids.
// Operating point: 29.5-30.7us kernel = 7.4-7.7 TB/s actual DRAM traffic
// = 94-96% of 8 TB/s spec (theoretical floor 28.3us).

static constexpr int TOTAL8 = 64 * 576 * 96;   // 3,538,944 x 32B
static constexpr int TPB    = 256;
static constexpr int UNROLL = 4;
static constexpr int TILE   = TPB * UNROLL;    // 1024
static constexpr int BLOCKS = TOTAL8 / TILE;   // 3456 exactly, no tail

// i in float8 (32B) units over the output.
__device__ __forceinline__ long long in_off8(int i)
{
    int e     = i % 96;           // float8 within patch (96 per patch)
    int t     = i / 96;
    int patch = t % 576;
    int b     = t / 576;

    int gy   = patch / 24;
    int gx   = patch - gy * 24;
    int py   = e / 6;
    int lane = e - py * 6;

    int y = gy * 16 + py;
    return (long long)(b * 384 + y) * 144 + gx * 6 + lane;  // float8 units
}

__device__ __forceinline__ void ldg256(const float* p, float4& a, float4& b)
{
    asm volatile("ld.global.nc.v8.f32 {%0,%1,%2,%3,%4,%5,%6,%7}, [%8];"
                 : "=f"(a.x), "=f"(a.y), "=f"(a.z), "=f"(a.w),
                   "=f"(b.x), "=f"(b.y), "=f"(b.z), "=f"(b.w)
                 : "l"(p));
}

__device__ __forceinline__ void stg256(float* p, const float4& a, const float4& b)
{
    asm volatile("st.global.v8.f32 [%0], {%1,%2,%3,%4,%5,%6,%7,%8};"
                 :: "l"(p),
                    "f"(a.x), "f"(a.y), "f"(a.z), "f"(a.w),
                    "f"(b.x), "f"(b.y), "f"(b.z), "f"(b.w)
                 : "memory");
}

__global__ void __launch_bounds__(TPB)
patches_kernel(const float* __restrict__ in, float* __restrict__ out)
{
    int base = blockIdx.x * TILE + threadIdx.x;

    const float* src[UNROLL];
#pragma unroll
    for (int u = 0; u < UNROLL; ++u)
        src[u] = in + in_off8(base + u * TPB) * 8;

    float4 a[UNROLL], b[UNROLL];
#pragma unroll
    for (int u = 0; u < UNROLL; ++u)
        ldg256(src[u], a[u], b[u]);

#pragma unroll
    for (int u = 0; u < UNROLL; ++u)
        stg256(out + (long long)(base + u * TPB) * 8, a[u], b[u]);
}

extern "C" void kernel_launch(void* const* d_in, const int* in_sizes, int n_in,
                              void* d_out, int out_size)
{
    (void)in_sizes; (void)n_in; (void)out_size;
    const float* in  = (const float*)d_in[0];
    float*       out = (float*)d_out;

    patches_kernel<<<BLOCKS, TPB>>>(in, out);
}